// round 17
// baseline (speedup 1.0000x reference)
#include <cuda_runtime.h>
#include <cuda_bf16.h>
#include <math.h>
#include <stdint.h>

// Problem dims (fixed by setup_inputs)
#define Bsz 512
#define Dsz 128
#define Isz 64
#define Hd  256           // decoder hidden
#define HeN 512           // encoder hidden
#define KeTOT (Isz + HeN) // 576

// ---------------- device scratch (static, no allocations) ----------------
__device__ __nv_bfloat16 g_We_hi[4 * HeN][KeTOT];  // [n'=u*4+g][k]
__device__ __nv_bfloat16 g_We_lo[4 * HeN][KeTOT];
__device__ __nv_bfloat16 g_Wd_hi[4 * Hd][Hd];
__device__ __nv_bfloat16 g_Wd_lo[4 * Hd][Hd];
__device__ __nv_bfloat16 g_Wo_hi[Isz][Hd];         // Wout^T split, [n][k]
__device__ __nv_bfloat16 g_Wo_lo[Isz][Hd];
__device__ __nv_bfloat16 g_Xe_hi[Dsz][Bsz][Isz];   // X_imp split, [t][m][k]
__device__ __nv_bfloat16 g_Xe_lo[Dsz][Bsz][Isz];
__device__ __nv_bfloat16 g_he_hi[2][Bsz][HeN];     // encoder h ping-pong (split)
__device__ __nv_bfloat16 g_he_lo[2][Bsz][HeN];
__device__ __nv_bfloat16 g_hs_hi[Dsz][Bsz][Hd];    // decoder h sequence (split);
__device__ __nv_bfloat16 g_hs_lo[Dsz][Bsz][Hd];    //   doubles as the dec recurrence buffer
// dependency-scoped step barriers: one counter per bm-row group (256B stride)
__device__ unsigned int g_bar_eg[4][64];           // encoder: 32 CTAs per group
__device__ unsigned int g_bar_dg[8][64];           // decoder: 16 CTAs per group

// fast transcendentals (error ~1e-6 rel; budget is 1e-3, current rel_err 8e-6)
__device__ __forceinline__ float sigm(float x) {
    return __fdividef(1.0f, 1.0f + __expf(-x));
}
__device__ __forceinline__ float tanh_fast(float x) {
    return 1.0f - __fdividef(2.0f, __expf(2.0f * x) + 1.0f);
}

// ---------------- low-level helpers ----------------
__device__ __forceinline__ uint32_t smem_u32(const void* p) {
    uint32_t a;
    asm("{ .reg .u64 t; cvta.to.shared.u64 t, %1; cvt.u32.u64 %0, t; }" : "=r"(a) : "l"(p));
    return a;
}
#define CP16(dst, src) \
    asm volatile("cp.async.cg.shared.global [%0], [%1], 16;" :: "r"(dst), "l"(src) : "memory")
#define CP_COMMIT() asm volatile("cp.async.commit_group;" ::: "memory")
#define CP_WAIT3()  asm volatile("cp.async.wait_group 3;" ::: "memory")
#define CP_WAIT2()  asm volatile("cp.async.wait_group 2;" ::: "memory")
#define CP_WAIT1()  asm volatile("cp.async.wait_group 1;" ::: "memory")
#define CP_WAIT0()  asm volatile("cp.async.wait_group 0;" ::: "memory")

__device__ __forceinline__ void ldsm4(uint32_t* d, uint32_t addr) {
    asm volatile("ldmatrix.sync.aligned.m8n8.x4.shared.b16 {%0,%1,%2,%3}, [%4];"
        : "=r"(d[0]), "=r"(d[1]), "=r"(d[2]), "=r"(d[3]) : "r"(addr));
}
__device__ __forceinline__ void mma16816(float* c, const uint32_t* a, uint32_t b0, uint32_t b1) {
    asm volatile("mma.sync.aligned.m16n8k16.row.col.f32.bf16.bf16.f32 "
        "{%0,%1,%2,%3}, {%4,%5,%6,%7}, {%8,%9}, {%0,%1,%2,%3};"
        : "+f"(c[0]), "+f"(c[1]), "+f"(c[2]), "+f"(c[3])
        : "r"(a[0]), "r"(a[1]), "r"(a[2]), "r"(a[3]), "r"(b0), "r"(b1));
}

// 128B-row tiles with XOR swizzle (Swizzle<3,4,3>): bits[6:4] ^= bits[9:7]
__device__ __forceinline__ uint32_t swz(uint32_t off) { return off ^ ((off >> 3) & 0x70); }

// ---- encoder persistent layout (K-chunks of 64) ----
#define E_WCH   16384                    // weight chunk: 64 rows x 128B, hi + lo
#define E_WS_SZ (9 * E_WCH)              // 147456 B resident weights
#define E_AST   32768                    // A stage: 128 rows x 128B, hi + lo
#define E_A0    E_WS_SZ
#define E_CONST (E_A0 + 2 * E_AST)       // 212992
#define E_HST   (E_CONST + 512)          // h staging: 128x16 bf16 hi (4KB) + lo (4KB)
#define E_SMEMP (E_HST + 8192)           // 221696 B
// ---- decoder persistent layout ----
#define D_WCH   16384
#define D_WS_SZ (4 * D_WCH)              // 65536 B
#define D_AST   16384                    // 64 rows x 128B, hi + lo
#define D_A0    D_WS_SZ
#define D_CONST (D_A0 + 2 * D_AST)       // 98304
#define D_HST   (D_CONST + 512)          // hi 2KB + lo 2KB (z bounce uses all 4KB)
#define D_SMEMP (D_HST + 4096)           // 102912 B
// ---- out_mma layout: Wout resident (4 chunks) + A stages ----
#define OM_WCH  16384
#define OM_WS   (4 * OM_WCH)             // 65536
#define OM_AST  32768                    // 128 rows x 128B, hi + lo
#define OM_A0   OM_WS
#define OM_CONST (OM_A0 + 2 * OM_AST)    // 131072
#define OM_SMEM (OM_CONST + 256)         // 131328

// ---------------- prep kernels ----------------
__global__ void conv_We_kernel(const float* __restrict__ Wx, const float* __restrict__ Wh) {
    int idx = blockIdx.x * 256 + threadIdx.x;
    if (idx >= 4 * HeN * KeTOT) return;
    int n = idx / KeTOT, k = idx % KeTOT;
    int u = n >> 2, g = n & 3, col = g * HeN + u;
    float w = (k < Isz) ? Wx[k * (4 * HeN) + col] : Wh[(k - Isz) * (4 * HeN) + col];
    __nv_bfloat16 hi = __float2bfloat16(w);
    g_We_hi[n][k] = hi;
    g_We_lo[n][k] = __float2bfloat16(w - __bfloat162float(hi));
}
__global__ void conv_Wd_kernel(const float* __restrict__ Wh, const float* __restrict__ Wout) {
    int idx = blockIdx.x * 256 + threadIdx.x;
    if (idx < Isz * Hd) {
        int n = idx / Hd, k = idx % Hd;
        float w = Wout[k * Isz + n];
        __nv_bfloat16 hi = __float2bfloat16(w);
        g_Wo_hi[n][k] = hi;
        g_Wo_lo[n][k] = __float2bfloat16(w - __bfloat162float(hi));
    }
    if (idx >= 4 * Hd * Hd) return;
    int n = idx / Hd, k = idx % Hd;
    int u = n >> 2, g = n & 3, col = g * Hd + u;
    float w = Wh[k * (4 * Hd) + col];
    __nv_bfloat16 hi = __float2bfloat16(w);
    g_Wd_hi[n][k] = hi;
    g_Wd_lo[n][k] = __float2bfloat16(w - __bfloat162float(hi));
}
__global__ void conv_X_kernel(const float* __restrict__ X, const float* __restrict__ Wm,
                              const float* __restrict__ A) {
    int idx = blockIdx.x * 256 + threadIdx.x;
    if (idx >= Dsz * Bsz * Isz) return;
    int t = idx / (Bsz * Isz);
    int r = idx % (Bsz * Isz);
    int m = r / Isz, k = r % Isz;
    int src = (m * Dsz + t) * Isz + k;
    float w = Wm[src];
    float v = X[src] * w + A[t * Isz + k] * (1.0f - w);
    __nv_bfloat16 hi = __float2bfloat16(v);
    g_Xe_hi[t][m][k] = hi;
    g_Xe_lo[t][m][k] = __float2bfloat16(v - __bfloat162float(hi));
}
__global__ void init_enc_kernel() {
    int i = blockIdx.x * 256 + threadIdx.x;
    if (i < 4) g_bar_eg[i][0] = 0u;
    if (i < 8) g_bar_dg[i][0] = 0u;
    if (i >= Bsz * HeN) return;
    __nv_bfloat16 z = __float2bfloat16(0.0f);
    (&g_he_hi[0][0][0])[i] = z;
    (&g_he_lo[0][0][0])[i] = z;
}

// ---------------- small outputs (accurate math; negligible cost) ----------------
__global__ void small_kernel(const float* __restrict__ mu_c_raw,
                             const float* __restrict__ sig_lat,
                             const float* __restrict__ phi_lat,
                             float* __restrict__ out_muc,
                             float* __restrict__ out_sig,
                             float* __restrict__ out_phi) {
    int tid = threadIdx.x;
    for (int i = tid; i < 8 * Hd; i += blockDim.x) {
        out_muc[i] = mu_c_raw[i];
        float v = sig_lat[i];
        out_sig[i] = fmaxf(v, 0.0f) + log1pf(expf(-fabsf(v)));
    }
    if (tid == 0) {
        float m = -1e30f;
        for (int i = 0; i < 8; ++i) m = fmaxf(m, phi_lat[i]);
        float e[8]; float s = 0.0f;
        for (int i = 0; i < 8; ++i) { e[i] = expf(phi_lat[i] - m); s += e[i]; }
        float inv = 1.0f / s;
        for (int i = 0; i < 8; ++i) out_phi[i] = e[i] * inv;
    }
}

// ============================================================================
// Persistent encoder: grid (4, 32), 256 threads (8 warps), 1 CTA/SM.
// CTA tile M=128, N=64. Warp: rows (wid&3)*32, cols (wid>>2)*32.
// K-chunks of 64 (9 chunks). A-hi and A-lo are SEPARATE cp.async groups:
// wait_group 3 -> hi landed -> Ah passes (Bh fragments saved in regs);
// wait_group 2 -> lo landed -> Al.Bh pass. Fragment-layout gates; c reg-
// resident; per-bm-group step barrier (32 CTAs per group).
// ============================================================================
__global__ void __launch_bounds__(256, 1) enc_persist(
    const float* __restrict__ bias,
    const float* __restrict__ wci, const float* __restrict__ wcf,
    const float* __restrict__ wco) {
    extern __shared__ char smem[];
    const uint32_t sb = smem_u32(smem);
    const int tid = threadIdx.x, wid = tid >> 5, lane = tid & 31;
    const int rw = wid & 3, cw = wid >> 2;
    const int bm0 = blockIdx.x * 128;
    const int n0  = blockIdx.y * 64;
    const int U0  = n0 >> 2;
    unsigned int* mybar = &g_bar_eg[blockIdx.x][0];

    // ---- one-time: resident weight slab ----
#pragma unroll
    for (int c = 0; c < 9; ++c) {
        uint32_t wb = sb + c * E_WCH;
#pragma unroll
        for (int j = 0; j < 2; ++j) {
            int flat = tid + j * 256;
            int row = flat >> 3, c16 = flat & 7;
            uint32_t off = swz(row * 128 + c16 * 16);
            CP16(wb + off,        &g_We_hi[n0 + row][c * 64 + c16 * 8]);
            CP16(wb + 8192 + off, &g_We_lo[n0 + row][c * 64 + c16 * 8]);
        }
    }
    CP_COMMIT();
    float* csm = (float*)(smem + E_CONST);
    if (tid < 16) {
        int u = U0 + tid;
        csm[tid]      = bias[u];
        csm[16 + tid] = bias[HeN + u];
        csm[32 + tid] = bias[2 * HeN + u];
        csm[48 + tid] = bias[3 * HeN + u];
        csm[64 + tid] = wci[u];
        csm[80 + tid] = wcf[u];
        csm[96 + tid] = wco[u];
    }
    CP_WAIT0();
    __syncthreads();

    // A-issue halves: 128 rows x 64 k (hi or lo), 4 CP16 per thread each
#define E_AISSUE_H(ah_, ap_, kb_, s_) do { \
        uint32_t so_ = sb + E_A0 + (s_) * E_AST; \
        _Pragma("unroll") \
        for (int j = 0; j < 4; ++j) { \
            int flat = tid + j * 256; \
            int row = flat >> 3, c16 = flat & 7; \
            uint32_t off = swz(row * 128 + c16 * 16); \
            CP16(so_ + off, (ah_) + (bm0 + row) * (ap_) + (kb_) + c16 * 8); \
        } \
    } while (0)
#define E_AISSUE_L(al_, ap_, kb_, s_) do { \
        uint32_t so_ = sb + E_A0 + (s_) * E_AST + 16384; \
        _Pragma("unroll") \
        for (int j = 0; j < 4; ++j) { \
            int flat = tid + j * 256; \
            int row = flat >> 3, c16 = flat & 7; \
            uint32_t off = swz(row * 128 + c16 * 16); \
            CP16(so_ + off, (al_) + (bm0 + row) * (ap_) + (kb_) + c16 * 8); \
        } \
    } while (0)

    // prefetch X chunk of step 0 into stage 0 (hi group, lo group)
    E_AISSUE_H((&g_Xe_hi[0][0][0]), Isz, 0, 0); CP_COMMIT();
    E_AISSUE_L((&g_Xe_lo[0][0][0]), Isz, 0, 0); CP_COMMIT();

    const int a_row = (lane & 7) + ((lane >> 3) & 1) * 8;
    const int a_kb  = ((lane >> 4) & 1) * 16;
    const int b_row = (lane & 7) + (lane >> 4) * 8;
    const int b_kb  = ((lane >> 3) & 1) * 16;
    const uint32_t lxor = (uint32_t)((lane & 7) << 4);
    const int q = lane & 3;
    const bool evn = (q & 1) == 0;
    unsigned short* hsh = (unsigned short*)(smem + E_HST);
    unsigned short* hsl = (unsigned short*)(smem + E_HST + 4096);

    float creg[8] = {0.f, 0.f, 0.f, 0.f, 0.f, 0.f, 0.f, 0.f};

    for (int t = 0; t < Dsz; ++t) {
        const int buf = t & 1;
        const __nv_bfloat16* __restrict__ hhi = &g_he_hi[buf][0][0];
        const __nv_bfloat16* __restrict__ hlo = &g_he_lo[buf][0][0];

        // chunk 1 (h) -> stage 1 (hi group, lo group)
        E_AISSUE_H(hhi, HeN, 0, 1); CP_COMMIT();
        E_AISSUE_L(hlo, HeN, 0, 1); CP_COMMIT();

        float acc[2][4][4];
#pragma unroll
        for (int mt = 0; mt < 2; ++mt)
#pragma unroll
            for (int nt = 0; nt < 4; ++nt)
#pragma unroll
                for (int r = 0; r < 4; ++r) acc[mt][nt][r] = 0.0f;

        for (int c = 0; c < 9; ++c) {
            const uint32_t so = sb + E_A0 + (c & 1) * E_AST;
            const uint32_t wb = sb + c * E_WCH;
            uint32_t BhS[4][2][4];
            // ---- pass A: hi of A landed (all but newest 3 groups complete) ----
            CP_WAIT3();
            __syncthreads();
#pragma unroll
            for (int ks = 0; ks < 4; ++ks) {
                uint32_t Ah[2][4], Bl[2][4];
#pragma unroll
                for (int mt = 0; mt < 2; ++mt) {
                    uint32_t ra = so + (uint32_t)(rw * 32 + mt * 16 + a_row) * 128
                                + (((uint32_t)(ks * 32 + a_kb)) ^ lxor);
                    ldsm4(Ah[mt], ra);
                }
#pragma unroll
                for (int np = 0; np < 2; ++np) {
                    uint32_t rb = wb + (uint32_t)(cw * 32 + np * 16 + b_row) * 128
                                + (((uint32_t)(ks * 32 + b_kb)) ^ lxor);
                    ldsm4(BhS[ks][np], rb);
                    ldsm4(Bl[np], rb + 8192);
                }
#pragma unroll
                for (int mt = 0; mt < 2; ++mt)
#pragma unroll
                    for (int np = 0; np < 2; ++np) {
                        mma16816(acc[mt][2 * np],     Ah[mt], BhS[ks][np][0], BhS[ks][np][1]);
                        mma16816(acc[mt][2 * np + 1], Ah[mt], BhS[ks][np][2], BhS[ks][np][3]);
                        mma16816(acc[mt][2 * np],     Ah[mt], Bl[np][0], Bl[np][1]);
                        mma16816(acc[mt][2 * np + 1], Ah[mt], Bl[np][2], Bl[np][3]);
                    }
            }
            // ---- pass B: lo of A landed ----
            CP_WAIT2();
            __syncthreads();
#pragma unroll
            for (int ks = 0; ks < 4; ++ks) {
                uint32_t Al[2][4];
#pragma unroll
                for (int mt = 0; mt < 2; ++mt) {
                    uint32_t ra = so + (uint32_t)(rw * 32 + mt * 16 + a_row) * 128
                                + (((uint32_t)(ks * 32 + a_kb)) ^ lxor) + 16384;
                    ldsm4(Al[mt], ra);
                }
#pragma unroll
                for (int mt = 0; mt < 2; ++mt)
#pragma unroll
                    for (int np = 0; np < 2; ++np) {
                        mma16816(acc[mt][2 * np],     Al[mt], BhS[ks][np][0], BhS[ks][np][1]);
                        mma16816(acc[mt][2 * np + 1], Al[mt], BhS[ks][np][2], BhS[ks][np][3]);
                    }
            }
            __syncthreads();
            if (c + 2 <= 8) {
                E_AISSUE_H(hhi, HeN, (c + 1) * 64, (c & 1)); CP_COMMIT();
                E_AISSUE_L(hlo, HeN, (c + 1) * 64, (c & 1)); CP_COMMIT();
            } else {
                CP_COMMIT(); CP_COMMIT();   // keep group window aligned
            }
        }

        // ---- gates directly in fragment layout ----
#pragma unroll
        for (int mt = 0; mt < 2; ++mt)
#pragma unroll
            for (int nt = 0; nt < 4; ++nt) {
                float a0 = acc[mt][nt][0], a1 = acc[mt][nt][1];
                float a2 = acc[mt][nt][2], a3 = acc[mt][nt][3];
                float v0 = __shfl_xor_sync(0xffffffffu, evn ? a2 : a0, 1);
                float v1 = __shfl_xor_sync(0xffffffffu, evn ? a3 : a1, 1);
                float zi = evn ? a0 : v0;
                float zf = evn ? a1 : v1;
                float zg = evn ? v0 : a2;
                float zo = evn ? v1 : a3;
                int ul = cw * 8 + nt * 2 + (q >> 1);
                int myrow = rw * 32 + mt * 16 + (lane >> 2) + (evn ? 0 : 8);
                float c_old = creg[mt * 4 + nt];
                zi += csm[ul]; zf += csm[16 + ul]; zg += csm[32 + ul]; zo += csm[48 + ul];
                float ig = sigm(zi + c_old * csm[64 + ul]);
                float fg = sigm(zf + c_old * csm[80 + ul]);
                float cn = fg * c_old + ig * tanh_fast(zg);
                float og = sigm(zo + cn * csm[96 + ul]);
                float h  = og * tanh_fast(cn);
                creg[mt * 4 + nt] = cn;
                __nv_bfloat16 hb = __float2bfloat16(h);
                hsh[myrow * 16 + ul] = __bfloat16_as_ushort(hb);
                hsl[myrow * 16 + ul] = __bfloat16_as_ushort(__float2bfloat16(h - __bfloat162float(hb)));
            }
        __syncthreads();

        // ---- coalesced h copy-out ----
        {
            int r = tid & 127;
            const uint4* src = (const uint4*)((tid < 128 ? (char*)hsh : (char*)hsl) + r * 32);
            uint4* dst = (tid < 128) ? (uint4*)&g_he_hi[buf ^ 1][bm0 + r][U0]
                                     : (uint4*)&g_he_lo[buf ^ 1][bm0 + r][U0];
            dst[0] = src[0];
            dst[1] = src[1];
        }

        if (t + 1 < Dsz) {
            E_AISSUE_H((&g_Xe_hi[t + 1][0][0]), Isz, 0, 0); CP_COMMIT();
            E_AISSUE_L((&g_Xe_lo[t + 1][0][0]), Isz, 0, 0); CP_COMMIT();

            __threadfence();
            __syncthreads();
            if (tid == 0) {
                atomicAdd(mybar, 1u);
                unsigned int target = 32u * (unsigned int)(t + 1);
                while (*(volatile unsigned int*)mybar < target) { }
                __threadfence();
            }
            __syncthreads();
        }
    }
#undef E_AISSUE_H
#undef E_AISSUE_L
}

// ============================================================================
// Persistent decoder: grid (8, 16), 256 threads (8 warps), 1 CTA/SM.
// CTA tile M=64, N=64. K-chunks of 64 (4 chunks). Fragment-layout gates;
// c register-resident; z computed in-kernel (fused z_kernel). h sequence
// stored split-bf16 in g_hs_hi/lo[t] (doubles as recurrence buffer).
// ============================================================================
__global__ void __launch_bounds__(256, 1) dec_persist(
    const float* __restrict__ bias,
    const float* __restrict__ wci, const float* __restrict__ wcf,
    const float* __restrict__ wco,
    const float* __restrict__ noise,
    float* __restrict__ out_z, float* __restrict__ out_mu,
    float* __restrict__ out_ls) {
    extern __shared__ char smem[];
    const uint32_t sb = smem_u32(smem);
    const int tid = threadIdx.x, wid = tid >> 5, lane = tid & 31;
    const int rw = wid & 1, cw = wid >> 1;
    const int bm0 = blockIdx.x * 64;
    const int n0  = blockIdx.y * 64;
    const int U0  = n0 >> 2;
    unsigned int* mybar = &g_bar_dg[blockIdx.x][0];

    // ---- one-time: resident weight slab ----
#pragma unroll
    for (int c = 0; c < 4; ++c) {
        uint32_t wb = sb + c * D_WCH;
#pragma unroll
        for (int j = 0; j < 2; ++j) {
            int flat = tid + j * 256;
            int row = flat >> 3, c16 = flat & 7;
            uint32_t off = swz(row * 128 + c16 * 16);
            CP16(wb + off,        &g_Wd_hi[n0 + row][c * 64 + c16 * 8]);
            CP16(wb + 8192 + off, &g_Wd_lo[n0 + row][c * 64 + c16 * 8]);
        }
    }
    CP_COMMIT();
    float* csm = (float*)(smem + D_CONST);
    if (tid < 16) {
        int u = U0 + tid;
        csm[tid]      = bias[u];
        csm[16 + tid] = bias[Hd + u];
        csm[32 + tid] = bias[2 * Hd + u];
        csm[48 + tid] = bias[3 * Hd + u];
        csm[64 + tid] = wci[u];
        csm[80 + tid] = wcf[u];
        csm[96 + tid] = wco[u];
    }

    // ---- fused z: this CTA owns rows [bm0,bm0+64), units [U0,U0+16) ----
    float* zsm = (float*)(smem + D_HST);   // 64x16 fp32 = 4KB bounce
#pragma unroll
    for (int j = 0; j < 4; ++j) {
        int i = tid + j * 256;             // 0..1023
        int r = i >> 4, u = i & 15;
        int grow = bm0 + r, gu = U0 + u;
        float mu = __bfloat162float(g_he_hi[0][grow][gu]) + __bfloat162float(g_he_lo[0][grow][gu]);
        float ls = __bfloat162float(g_he_hi[0][grow][Hd + gu]) + __bfloat162float(g_he_lo[0][grow][Hd + gu]);
        float zz = mu + expf(0.5f * ls) * noise[grow * Hd + gu];
        int oi = grow * Hd + gu;
        out_mu[oi] = mu;
        out_ls[oi] = ls;
        out_z[oi]  = zz;
        zsm[i] = zz;
    }
    CP_WAIT0();
    __syncthreads();

    const int a_row = (lane & 7) + ((lane >> 3) & 1) * 8;
    const int a_kb  = ((lane >> 4) & 1) * 16;
    const int b_row = (lane & 7) + (lane >> 4) * 8;
    const int b_kb  = ((lane >> 3) & 1) * 16;
    const uint32_t lxor = (uint32_t)((lane & 7) << 4);
    const int q = lane & 3;
    const bool evn = (q & 1) == 0;
    unsigned short* hsh = (unsigned short*)(smem + D_HST);
    unsigned short* hsl = (unsigned short*)(smem + D_HST + 2048);

    // register-resident c in fragment layout; c0 = z (from smem bounce)
    float creg[4];
#pragma unroll
    for (int mt = 0; mt < 2; ++mt)
#pragma unroll
        for (int nt = 0; nt < 2; ++nt) {
            int ul = cw * 4 + nt * 2 + (q >> 1);
            int myrow = rw * 32 + mt * 16 + (lane >> 2) + (evn ? 0 : 8);
            creg[mt * 2 + nt] = zsm[myrow * 16 + ul];
        }
    __syncthreads();   // creg reads done before hsh/hsl overwrite zsm

    for (int t = 0; t < Dsz; ++t) {
        float acc[2][2][4];
#pragma unroll
        for (int mt = 0; mt < 2; ++mt)
#pragma unroll
            for (int nt = 0; nt < 2; ++nt)
#pragma unroll
                for (int r = 0; r < 4; ++r) acc[mt][nt][r] = 0.0f;

        if (t > 0) {
            const __nv_bfloat16* __restrict__ hhi = &g_hs_hi[t - 1][0][0];
            const __nv_bfloat16* __restrict__ hlo = &g_hs_lo[t - 1][0][0];

#define D_AISSUE(c, s) do { \
            uint32_t so_ = sb + D_A0 + (s) * D_AST; \
            int kb_ = (c) * 64; \
            _Pragma("unroll") \
            for (int j = 0; j < 2; ++j) { \
                int flat = tid + j * 256; \
                int row = flat >> 3, c16 = flat & 7; \
                uint32_t off = swz(row * 128 + c16 * 16); \
                CP16(so_ + off,        hhi + (bm0 + row) * Hd + kb_ + c16 * 8); \
                CP16(so_ + 8192 + off, hlo + (bm0 + row) * Hd + kb_ + c16 * 8); \
            } \
        } while (0)

            D_AISSUE(0, 0); CP_COMMIT();
            D_AISSUE(1, 1); CP_COMMIT();

            for (int c = 0; c < 4; ++c) {
                CP_WAIT1();
                __syncthreads();
                const uint32_t so = sb + D_A0 + (c & 1) * D_AST;
                const uint32_t wb = sb + c * D_WCH;
#pragma unroll
                for (int ks = 0; ks < 4; ++ks) {
                    uint32_t Ah[2][4], Al[2][4], Bh[4], Bl[4];
#pragma unroll
                    for (int mt = 0; mt < 2; ++mt) {
                        uint32_t ra = so + (uint32_t)(rw * 32 + mt * 16 + a_row) * 128
                                    + (((uint32_t)(ks * 32 + a_kb)) ^ lxor);
                        ldsm4(Ah[mt], ra);
                        ldsm4(Al[mt], ra + 8192);
                    }
                    uint32_t rb = wb + (uint32_t)(cw * 16 + b_row) * 128
                                + (((uint32_t)(ks * 32 + b_kb)) ^ lxor);
                    ldsm4(Bh, rb);
                    ldsm4(Bl, rb + 8192);
#pragma unroll
                    for (int mt = 0; mt < 2; ++mt) {
                        mma16816(acc[mt][0], Ah[mt], Bh[0], Bh[1]);
                        mma16816(acc[mt][1], Ah[mt], Bh[2], Bh[3]);
                        mma16816(acc[mt][0], Ah[mt], Bl[0], Bl[1]);
                        mma16816(acc[mt][1], Ah[mt], Bl[2], Bl[3]);
                        mma16816(acc[mt][0], Al[mt], Bh[0], Bh[1]);
                        mma16816(acc[mt][1], Al[mt], Bh[2], Bh[3]);
                    }
                }
                __syncthreads();
                if (c + 2 <= 3) { D_AISSUE(c + 2, c & 1); }
                CP_COMMIT();
            }
#undef D_AISSUE
            CP_WAIT0();
        }

        // ---- gates in fragment layout ----
#pragma unroll
        for (int mt = 0; mt < 2; ++mt)
#pragma unroll
            for (int nt = 0; nt < 2; ++nt) {
                float a0 = acc[mt][nt][0], a1 = acc[mt][nt][1];
                float a2 = acc[mt][nt][2], a3 = acc[mt][nt][3];
                float v0 = __shfl_xor_sync(0xffffffffu, evn ? a2 : a0, 1);
                float v1 = __shfl_xor_sync(0xffffffffu, evn ? a3 : a1, 1);
                float zi = evn ? a0 : v0;
                float zf = evn ? a1 : v1;
                float zg = evn ? v0 : a2;
                float zo = evn ? v1 : a3;
                int ul = cw * 4 + nt * 2 + (q >> 1);
                int myrow = rw * 32 + mt * 16 + (lane >> 2) + (evn ? 0 : 8);
                float c_old = creg[mt * 2 + nt];
                zi += csm[ul]; zf += csm[16 + ul]; zg += csm[32 + ul]; zo += csm[48 + ul];
                float ig = sigm(zi + c_old * csm[64 + ul]);
                float fg = sigm(zf + c_old * csm[80 + ul]);
                float cn = fg * c_old + ig * tanh_fast(zg);
                float og = sigm(zo + cn * csm[96 + ul]);
                float h  = og * tanh_fast(cn);
                creg[mt * 2 + nt] = cn;
                __nv_bfloat16 hb = __float2bfloat16(h);
                hsh[myrow * 16 + ul] = __bfloat16_as_ushort(hb);
                hsl[myrow * 16 + ul] = __bfloat16_as_ushort(__float2bfloat16(h - __bfloat162float(hb)));
            }
        __syncthreads();

        // ---- coalesced copy-out to the h sequence (also recurrence buffer) ----
        if (tid < 64) {
            int r = tid;
            const uint4* src = (const uint4*)((char*)hsh + r * 32);
            uint4* dst = (uint4*)&g_hs_hi[t][bm0 + r][U0];
            dst[0] = src[0]; dst[1] = src[1];
        } else if (tid < 128) {
            int r = tid - 64;
            const uint4* src = (const uint4*)((char*)hsl + r * 32);
            uint4* dst = (uint4*)&g_hs_lo[t][bm0 + r][U0];
            dst[0] = src[0]; dst[1] = src[1];
        }

        if (t + 1 < Dsz) {
            __threadfence();
            __syncthreads();
            if (tid == 0) {
                atomicAdd(mybar, 1u);
                unsigned int target = 16u * (unsigned int)(t + 1);
                while (*(volatile unsigned int*)mybar < target) { }
                __threadfence();
            }
            __syncthreads();
        }
    }
}

// ============================================================================
// Output projection via HMMA: out = hs @ Wout + bout; x = sigm(out).
// grid (Dsz, 4), 256 threads. CTA: M=128 batch rows, N=64 cols, K=256.
// ============================================================================
__global__ void __launch_bounds__(256) out_mma(
    const float* __restrict__ bout,
    float* __restrict__ out_x, float* __restrict__ out_xraw) {
    extern __shared__ char smem[];
    const uint32_t sb = smem_u32(smem);
    const int tid = threadIdx.x, wid = tid >> 5, lane = tid & 31;
    const int rw = wid & 3, cw = wid >> 2;
    const int t   = blockIdx.x;
    const int bm0 = blockIdx.y * 128;

#pragma unroll
    for (int c = 0; c < 4; ++c) {
        uint32_t wb = sb + c * OM_WCH;
#pragma unroll
        for (int j = 0; j < 2; ++j) {
            int flat = tid + j * 256;
            int row = flat >> 3, c16 = flat & 7;
            uint32_t off = swz(row * 128 + c16 * 16);
            CP16(wb + off,        &g_Wo_hi[row][c * 64 + c16 * 8]);
            CP16(wb + 8192 + off, &g_Wo_lo[row][c * 64 + c16 * 8]);
        }
    }
    CP_COMMIT();
    float* csm = (float*)(smem + OM_CONST);
    if (tid < 64) csm[tid] = bout[tid];

#define O_AISSUE(c, s) do { \
        uint32_t so_ = sb + OM_A0 + (s) * OM_AST; \
        int kb_ = (c) * 64; \
        _Pragma("unroll") \
        for (int j = 0; j < 4; ++j) { \
            int flat = tid + j * 256; \
            int row = flat >> 3, c16 = flat & 7; \
            uint32_t off = swz(row * 128 + c16 * 16); \
            CP16(so_ + off,         &g_hs_hi[t][bm0 + row][kb_ + c16 * 8]); \
            CP16(so_ + 16384 + off, &g_hs_lo[t][bm0 + row][kb_ + c16 * 8]); \
        } \
    } while (0)

    O_AISSUE(0, 0); CP_COMMIT();
    O_AISSUE(1, 1); CP_COMMIT();

    const int a_row = (lane & 7) + ((lane >> 3) & 1) * 8;
    const int a_kb  = ((lane >> 4) & 1) * 16;
    const int b_row = (lane & 7) + (lane >> 4) * 8;
    const int b_kb  = ((lane >> 3) & 1) * 16;
    const uint32_t lxor = (uint32_t)((lane & 7) << 4);
    const int q = lane & 3;

    float acc[2][4][4];
#pragma unroll
    for (int mt = 0; mt < 2; ++mt)
#pragma unroll
        for (int nt = 0; nt < 4; ++nt)
#pragma unroll
            for (int r = 0; r < 4; ++r) acc[mt][nt][r] = 0.0f;

    for (int c = 0; c < 4; ++c) {
        CP_WAIT1();
        __syncthreads();
        const uint32_t so = sb + OM_A0 + (c & 1) * OM_AST;
        const uint32_t wb = sb + c * OM_WCH;
#pragma unroll
        for (int ks = 0; ks < 4; ++ks) {
            uint32_t Ah[2][4], Al[2][4], Bh[2][4], Bl[2][4];
#pragma unroll
            for (int mt = 0; mt < 2; ++mt) {
                uint32_t ra = so + (uint32_t)(rw * 32 + mt * 16 + a_row) * 128
                            + (((uint32_t)(ks * 32 + a_kb)) ^ lxor);
                ldsm4(Ah[mt], ra);
                ldsm4(Al[mt], ra + 16384);
            }
#pragma unroll
            for (int np = 0; np < 2; ++np) {
                uint32_t rb = wb + (uint32_t)(cw * 32 + np * 16 + b_row) * 128
                            + (((uint32_t)(ks * 32 + b_kb)) ^ lxor);
                ldsm4(Bh[np], rb);
                ldsm4(Bl[np], rb + 8192);
            }
#pragma unroll
            for (int mt = 0; mt < 2; ++mt)
#pragma unroll
                for (int np = 0; np < 2; ++np) {
                    mma16816(acc[mt][2 * np],     Ah[mt], Bh[np][0], Bh[np][1]);
                    mma16816(acc[mt][2 * np + 1], Ah[mt], Bh[np][2], Bh[np][3]);
                    mma16816(acc[mt][2 * np],     Ah[mt], Bl[np][0], Bl[np][1]);
                    mma16816(acc[mt][2 * np + 1], Ah[mt], Bl[np][2], Bl[np][3]);
                    mma16816(acc[mt][2 * np],     Al[mt], Bh[np][0], Bh[np][1]);
                    mma16816(acc[mt][2 * np + 1], Al[mt], Bh[np][2], Bh[np][3]);
                }
        }
        __syncthreads();
        if (c + 2 <= 3) { O_AISSUE(c + 2, c & 1); }
        CP_COMMIT();
    }
#undef O_AISSUE

#pragma unroll
    for (int mt = 0; mt < 2; ++mt)
#pragma unroll
        for (int nt = 0; nt < 4; ++nt) {
            int col = cw * 32 + nt * 8 + q * 2;
            float b0 = csm[col], b1 = csm[col + 1];
            int r0 = bm0 + rw * 32 + mt * 16 + (lane >> 2);
#pragma unroll
            for (int hh = 0; hh < 2; ++hh) {
                int row = r0 + hh * 8;
                float x0 = acc[mt][nt][2 * hh]     + b0;
                float x1 = acc[mt][nt][2 * hh + 1] + b1;
                int oi = (row * Dsz + t) * Isz + col;
                *(float2*)&out_xraw[oi] = make_float2(x0, x1);
                *(float2*)&out_x[oi]    = make_float2(sigm(x0), sigm(x1));
            }
        }
}

// ---------------- launch ----------------
extern "C" void kernel_launch(void* const* d_in, const int* in_sizes, int n_in,
                              void* d_out, int out_size) {
    (void)in_sizes; (void)n_in; (void)out_size;
    const float* X      = (const float*)d_in[0];
    const float* Wm     = (const float*)d_in[1];
    const float* noise  = (const float*)d_in[2];
    const float* A      = (const float*)d_in[3];
    const float* Wx_e   = (const float*)d_in[4];
    const float* Wh_e   = (const float*)d_in[5];
    const float* b_e    = (const float*)d_in[6];
    const float* wci_e  = (const float*)d_in[7];
    const float* wcf_e  = (const float*)d_in[8];
    const float* wco_e  = (const float*)d_in[9];
    // d_in[10] = Wx_d : unused (decoder inputs are zero)
    const float* Wh_d   = (const float*)d_in[11];
    const float* b_d    = (const float*)d_in[12];
    const float* wci_d  = (const float*)d_in[13];
    const float* wcf_d  = (const float*)d_in[14];
    const float* wco_d  = (const float*)d_in[15];
    const float* Wout   = (const float*)d_in[16];
    const float* bout   = (const float*)d_in[17];
    const float* mu_c_r = (const float*)d_in[18];
    const float* sig_l  = (const float*)d_in[19];
    const float* phi_l  = (const float*)d_in[20];

    float* out = (float*)d_out;
    float* out_x    = out;                 // 4194304
    float* out_xraw = out + 4194304;       // 4194304
    float* out_muc  = out + 8388608;       // 2048
    float* out_sig  = out + 8390656;       // 2048
    float* out_phi  = out + 8392704;       // 8
    float* out_z    = out + 8392712;       // 131072
    float* out_mu   = out + 8523784;       // 131072
    float* out_ls   = out + 8654856;       // 131072

    cudaFuncSetAttribute(enc_persist, cudaFuncAttributeMaxDynamicSharedMemorySize, E_SMEMP);
    cudaFuncSetAttribute(dec_persist, cudaFuncAttributeMaxDynamicSharedMemorySize, D_SMEMP);
    cudaFuncSetAttribute(out_mma,     cudaFuncAttributeMaxDynamicSharedMemorySize, OM_SMEM);

    conv_We_kernel<<<(4 * HeN * KeTOT + 255) / 256, 256>>>(Wx_e, Wh_e);
    conv_Wd_kernel<<<(4 * Hd * Hd + 255) / 256, 256>>>(Wh_d, Wout);
    conv_X_kernel<<<(Dsz * Bsz * Isz + 255) / 256, 256>>>(X, Wm, A);
    init_enc_kernel<<<(Bsz * HeN + 255) / 256, 256>>>();
    small_kernel<<<1, 256>>>(mu_c_r, sig_l, phi_l, out_muc, out_sig, out_phi);

    enc_persist<<<dim3(4, 32), 256, E_SMEMP>>>(b_e, wci_e, wcf_e, wco_e);

    dec_persist<<<dim3(8, 16), 256, D_SMEMP>>>(b_d, wci_d, wcf_d, wco_d,
                                               noise, out_z, out_mu, out_ls);

    out_mma<<<dim3(Dsz, 4), 256, OM_SMEM>>>(bout, out_x, out_xraw);
}